// round 5
// baseline (speedup 1.0000x reference)
#include <cuda_runtime.h>
#include <math.h>
#include <stdint.h>

#define DM 1024
#define SEQ 2048
#define NB 2
#define NH 16
#define HD 64
#define MTOT (NB*SEQ)   // 4096

// -------- scratch (static device memory; no runtime allocation) ----------
__device__ float g_q[MTOT * DM];
__device__ float g_k[MTOT * DM];
__device__ float g_v[MTOT * DM];
__device__ float g_ao[MTOT * DM];
__device__ float g_cos[SEQ * (HD / 2)];
__device__ float g_sin[SEQ * (HD / 2)];

// -------------------- helpers ---------------------
__device__ __forceinline__ uint32_t f2tf32(float x) {
    uint32_t r;
    asm("cvt.rna.tf32.f32 %0, %1;" : "=r"(r) : "f"(x));
    return r;
}

__device__ __forceinline__ void mma8(float* c, const uint32_t* a,
                                     uint32_t b0, uint32_t b1) {
    asm volatile(
        "mma.sync.aligned.m16n8k8.row.col.f32.tf32.tf32.f32 "
        "{%0,%1,%2,%3}, {%4,%5,%6,%7}, {%8,%9}, {%0,%1,%2,%3};\n"
        : "+f"(c[0]), "+f"(c[1]), "+f"(c[2]), "+f"(c[3])
        : "r"(a[0]), "r"(a[1]), "r"(a[2]), "r"(a[3]), "r"(b0), "r"(b1));
}

// -------------------- RoPE tables (double precision) ---------------------
__global__ void rope_table_kernel() {
    int p = threadIdx.x;      // 0..31 pair index
    int s = blockIdx.x;       // 0..2047 position
    double freq = pow(10000.0, -(double)(2 * p) / 64.0);
    double ang = (double)s * freq;
    g_cos[s * 32 + p] = (float)cos(ang);
    g_sin[s * 32 + p] = (float)sin(ang);
}

// ------------------- tf32 tensor-core GEMM: out = X @ W^T + b ------------
// Block tile 128x128, BK=32, 8 warps, warp tile 64x32.
// Double-buffered smem (one __syncthreads per K-tile).
// FUSED: grid.x = 24; block selects {wq,wk,wv} by blockIdx.x>>3, RoPE on q/k.
#define GSTR 36
#define GWORDS (128 * GSTR)
#define GEMM_SMEM (4 * GWORDS * 4)   // 2 bufs x (As+Bs) = 73728 B

template <bool FUSED>
__global__ __launch_bounds__(256) void gemm_tc(
    const float* __restrict__ X,
    const float* __restrict__ Wq, const float* __restrict__ Bq, float* __restrict__ Oq,
    const float* __restrict__ Wk, const float* __restrict__ Bk, float* __restrict__ Ok,
    const float* __restrict__ Wv, const float* __restrict__ Bv, float* __restrict__ Ov)
{
    extern __shared__ uint32_t gsm[];
    uint32_t* Asb[2] = {gsm, gsm + GWORDS};
    uint32_t* Bsb[2] = {gsm + 2 * GWORDS, gsm + 3 * GWORDS};

    const float* W;
    const float* bias;
    float* out;
    bool rope;
    int bx = blockIdx.x;
    if (FUSED) {
        int sel = bx >> 3;
        W    = sel == 0 ? Wq : (sel == 1 ? Wk : Wv);
        bias = sel == 0 ? Bq : (sel == 1 ? Bk : Bv);
        out  = sel == 0 ? Oq : (sel == 1 ? Ok : Ov);
        rope = (sel < 2);
        bx &= 7;
    } else {
        W = Wq; bias = Bq; out = Oq; rope = false;
    }

    const int tid  = threadIdx.x;
    const int lane = tid & 31;
    const int wid  = tid >> 5;
    const int g    = lane >> 2;
    const int tg   = lane & 3;
    const int wm   = (wid & 1) * 64;
    const int wn   = (wid >> 1) * 32;
    const int m0   = blockIdx.y * 128;
    const int n0   = bx * 128;

    float acc[4][4][4];
#pragma unroll
    for (int mi = 0; mi < 4; mi++)
#pragma unroll
        for (int ni = 0; ni < 4; ni++)
#pragma unroll
            for (int q = 0; q < 4; q++) acc[mi][ni][q] = 0.0f;

    float4 xa[4], wb[4];

    // prologue: load kt=0, stage into buffer 0
#pragma unroll
    for (int i = 0; i < 4; i++) {
        int f = tid + i * 256;
        int r = f >> 3, k4 = f & 7;
        xa[i] = *(const float4*)&X[(size_t)(m0 + r) * DM + k4 * 4];
        wb[i] = *(const float4*)&W[(size_t)(n0 + r) * DM + k4 * 4];
    }
#pragma unroll
    for (int i = 0; i < 4; i++) {
        int f = tid + i * 256;
        int r = f >> 3, k4 = f & 7;
        *(uint4*)&Asb[0][r * GSTR + k4 * 4] =
            make_uint4(f2tf32(xa[i].x), f2tf32(xa[i].y), f2tf32(xa[i].z), f2tf32(xa[i].w));
        *(uint4*)&Bsb[0][r * GSTR + k4 * 4] =
            make_uint4(f2tf32(wb[i].x), f2tf32(wb[i].y), f2tf32(wb[i].z), f2tf32(wb[i].w));
    }
    __syncthreads();

    int cur = 0;
    for (int kt = 0; kt < DM; kt += 32) {
        const bool nxt = (kt + 32 < DM);
        if (nxt) {
#pragma unroll
            for (int i = 0; i < 4; i++) {
                int f = tid + i * 256;
                int r = f >> 3, k4 = f & 7;
                xa[i] = *(const float4*)&X[(size_t)(m0 + r) * DM + kt + 32 + k4 * 4];
                wb[i] = *(const float4*)&W[(size_t)(n0 + r) * DM + kt + 32 + k4 * 4];
            }
        }

        const uint32_t* As = Asb[cur];
        const uint32_t* Bs = Bsb[cur];
#pragma unroll
        for (int ks = 0; ks < 32; ks += 8) {
            uint32_t a[4][4];
#pragma unroll
            for (int mi = 0; mi < 4; mi++) {
                int r0 = wm + mi * 16 + g;
                a[mi][0] = As[r0 * GSTR + ks + tg];
                a[mi][1] = As[(r0 + 8) * GSTR + ks + tg];
                a[mi][2] = As[r0 * GSTR + ks + tg + 4];
                a[mi][3] = As[(r0 + 8) * GSTR + ks + tg + 4];
            }
#pragma unroll
            for (int ni = 0; ni < 4; ni++) {
                int rb = wn + ni * 8 + g;
                uint32_t b0 = Bs[rb * GSTR + ks + tg];
                uint32_t b1 = Bs[rb * GSTR + ks + tg + 4];
#pragma unroll
                for (int mi = 0; mi < 4; mi++)
                    mma8(acc[mi][ni], a[mi], b0, b1);
            }
        }

        if (nxt) {
            uint32_t* An = Asb[cur ^ 1];
            uint32_t* Bn = Bsb[cur ^ 1];
#pragma unroll
            for (int i = 0; i < 4; i++) {
                int f = tid + i * 256;
                int r = f >> 3, k4 = f & 7;
                *(uint4*)&An[r * GSTR + k4 * 4] =
                    make_uint4(f2tf32(xa[i].x), f2tf32(xa[i].y), f2tf32(xa[i].z), f2tf32(xa[i].w));
                *(uint4*)&Bn[r * GSTR + k4 * 4] =
                    make_uint4(f2tf32(wb[i].x), f2tf32(wb[i].y), f2tf32(wb[i].z), f2tf32(wb[i].w));
            }
            __syncthreads();
            cur ^= 1;
        }
    }

    // epilogue: bias (+ RoPE) + store
#pragma unroll
    for (int mi = 0; mi < 4; mi++) {
        int row = m0 + wm + mi * 16 + g;
#pragma unroll
        for (int ni = 0; ni < 4; ni++) {
            int col = n0 + wn + ni * 8 + 2 * tg;
            float b0 = bias[col], b1 = bias[col + 1];
            float v0 = acc[mi][ni][0] + b0;
            float v1 = acc[mi][ni][1] + b1;
            float v2 = acc[mi][ni][2] + b0;
            float v3 = acc[mi][ni][3] + b1;
            if (rope) {
                int pr = (col & 63) >> 1;
                int s0 = row & (SEQ - 1);
                int s1 = (row + 8) & (SEQ - 1);
                float c0 = g_cos[s0 * 32 + pr], sn0 = g_sin[s0 * 32 + pr];
                float c1 = g_cos[s1 * 32 + pr], sn1 = g_sin[s1 * 32 + pr];
                float e = v0, o = v1;
                v0 = e * c0 - o * sn0;
                v1 = o * c0 + e * sn0;
                e = v2; o = v3;
                v2 = e * c1 - o * sn1;
                v3 = o * c1 + e * sn1;
            }
            *(float2*)&out[(size_t)row * DM + col]       = make_float2(v0, v1);
            *(float2*)&out[(size_t)(row + 8) * DM + col] = make_float2(v2, v3);
        }
    }
}

// --------------------------- flash attention (tf32 MMA) ------------------
// grid (SEQ/64, NB*NH), 128 threads = 4 warps, warp owns 16 query rows.
// Q fragments register-resident (staged once via the P buffer).
// smem: Ps 64x68 (Q staging + P), Ks 64x68, Vs 64x72 = 52 KB -> 3 CTAs/SM.
#define ASTR 68
#define AVSTR 72
#define ATT_WORDS (2 * 64 * ASTR + 64 * AVSTR)
#define ATT_SMEM (ATT_WORDS * 4)

__global__ __launch_bounds__(128, 3) void attn_tc()
{
    extern __shared__ uint32_t asm_[];
    uint32_t* Ps = asm_;                 // [64][68]
    uint32_t* Ks = asm_ + 64 * ASTR;     // [64][68]
    uint32_t* Vs = asm_ + 2 * 64 * ASTR; // [64][72]

    const int tid  = threadIdx.x;
    const int lane = tid & 31;
    const int wid  = tid >> 5;        // 0..3
    const int g    = lane >> 2;
    const int tg   = lane & 3;
    const int wq0  = wid * 16;

    const int q0 = blockIdx.x * 64;
    const int bh = blockIdx.y;
    const int b  = bh >> 4;
    const int h  = bh & 15;
    const float scale = 0.125f;

    const size_t base = (size_t)b * SEQ * DM + (size_t)h * HD;

    // stage Q tile (64x64) through Ps, then pull fragments into registers
#pragma unroll
    for (int i = 0; i < 8; i++) {
        int f = tid + i * 128;
        int s = f >> 4, dq = f & 15;
        float4 qv = *(const float4*)&g_q[base + (size_t)(q0 + s) * DM + dq * 4];
        *(uint4*)&Ps[s * ASTR + dq * 4] =
            make_uint4(f2tf32(qv.x * scale), f2tf32(qv.y * scale),
                       f2tf32(qv.z * scale), f2tf32(qv.w * scale));
    }
    __syncthreads();

    uint32_t qf[8][4];
#pragma unroll
    for (int ks = 0; ks < 8; ks++) {
        qf[ks][0] = Ps[(wq0 + g) * ASTR + ks * 8 + tg];
        qf[ks][1] = Ps[(wq0 + 8 + g) * ASTR + ks * 8 + tg];
        qf[ks][2] = Ps[(wq0 + g) * ASTR + ks * 8 + tg + 4];
        qf[ks][3] = Ps[(wq0 + 8 + g) * ASTR + ks * 8 + tg + 4];
    }
    // from here each warp only touches its own 16 rows of Ps -> no block sync

    float o[8][4];
    float mrow[2], lrow[2];
    mrow[0] = mrow[1] = -1e30f;
    lrow[0] = lrow[1] = 0.0f;
#pragma unroll
    for (int ni = 0; ni < 8; ni++)
#pragma unroll
        for (int q = 0; q < 4; q++) o[ni][q] = 0.0f;

    for (int kv0 = 0; kv0 < SEQ; kv0 += 64) {
        __syncthreads();   // previous tile's Ks/Vs reads complete
        // load K/V tiles (64x64 each)
#pragma unroll
        for (int i = 0; i < 8; i++) {
            int f = tid + i * 128;
            int s = f >> 4, dq = f & 15;
            float4 kv = *(const float4*)&g_k[base + (size_t)(kv0 + s) * DM + dq * 4];
            *(uint4*)&Ks[s * ASTR + dq * 4] =
                make_uint4(f2tf32(kv.x), f2tf32(kv.y), f2tf32(kv.z), f2tf32(kv.w));
            float4 vv = *(const float4*)&g_v[base + (size_t)(kv0 + s) * DM + dq * 4];
            *(uint4*)&Vs[s * AVSTR + dq * 4] =
                make_uint4(f2tf32(vv.x), f2tf32(vv.y), f2tf32(vv.z), f2tf32(vv.w));
        }
        __syncthreads();

        // ---- S = Q @ K^T (warp: 16 rows x 64 cols) ----
        float sc[8][4];
#pragma unroll
        for (int ni = 0; ni < 8; ni++)
#pragma unroll
            for (int q = 0; q < 4; q++) sc[ni][q] = 0.0f;

#pragma unroll
        for (int ks = 0; ks < 8; ks++) {
#pragma unroll
            for (int ni = 0; ni < 8; ni++) {
                int rb = ni * 8 + g;
                uint32_t b0 = Ks[rb * ASTR + ks * 8 + tg];
                uint32_t b1 = Ks[rb * ASTR + ks * 8 + tg + 4];
                mma8(sc[ni], qf[ks], b0, b1);
            }
        }

        // ---- online softmax (2 row groups: rows g and 8+g) ----
#pragma unroll
        for (int hf = 0; hf < 2; hf++) {
            float vmax = -1e30f;
#pragma unroll
            for (int ni = 0; ni < 8; ni++) {
                vmax = fmaxf(vmax, sc[ni][hf * 2]);
                vmax = fmaxf(vmax, sc[ni][hf * 2 + 1]);
            }
            vmax = fmaxf(vmax, __shfl_xor_sync(0xffffffffu, vmax, 1));
            vmax = fmaxf(vmax, __shfl_xor_sync(0xffffffffu, vmax, 2));
            float nm = fmaxf(mrow[hf], vmax);
            float alpha = __expf(mrow[hf] - nm);
            mrow[hf] = nm;
            float sum = 0.0f;
            int row = wq0 + hf * 8 + g;
#pragma unroll
            for (int ni = 0; ni < 8; ni++) {
                float px = __expf(sc[ni][hf * 2]     - nm);
                float py = __expf(sc[ni][hf * 2 + 1] - nm);
                sum += px + py;
                *(uint2*)&Ps[row * ASTR + ni * 8 + 2 * tg] =
                    make_uint2(f2tf32(px), f2tf32(py));
            }
            sum += __shfl_xor_sync(0xffffffffu, sum, 1);
            sum += __shfl_xor_sync(0xffffffffu, sum, 2);
            lrow[hf] = lrow[hf] * alpha + sum;
#pragma unroll
            for (int ni = 0; ni < 8; ni++) {
                o[ni][hf * 2]     *= alpha;
                o[ni][hf * 2 + 1] *= alpha;
            }
        }
        __syncwarp();

        // ---- O += P @ V (warp: 16 rows x 64 dims) ----
#pragma unroll
        for (int ks = 0; ks < 8; ks++) {
            uint32_t a[4];
            a[0] = Ps[(wq0 + g) * ASTR + ks * 8 + tg];
            a[1] = Ps[(wq0 + 8 + g) * ASTR + ks * 8 + tg];
            a[2] = Ps[(wq0 + g) * ASTR + ks * 8 + tg + 4];
            a[3] = Ps[(wq0 + 8 + g) * ASTR + ks * 8 + tg + 4];
#pragma unroll
            for (int ni = 0; ni < 8; ni++) {
                uint32_t b0 = Vs[(ks * 8 + tg) * AVSTR + ni * 8 + g];
                uint32_t b1 = Vs[(ks * 8 + tg + 4) * AVSTR + ni * 8 + g];
                mma8(o[ni], a, b0, b1);
            }
        }
    }

    // normalize + store
    float inv0 = 1.0f / lrow[0];
    float inv1 = 1.0f / lrow[1];
    int row = q0 + wq0 + g;
#pragma unroll
    for (int ni = 0; ni < 8; ni++) {
        int col = ni * 8 + 2 * tg;
        *(float2*)&g_ao[base + (size_t)row * DM + col] =
            make_float2(o[ni][0] * inv0, o[ni][1] * inv0);
        *(float2*)&g_ao[base + (size_t)(row + 8) * DM + col] =
            make_float2(o[ni][2] * inv1, o[ni][3] * inv1);
    }
}

// ------------------------------- launch ----------------------------------
extern "C" void kernel_launch(void* const* d_in, const int* in_sizes, int n_in,
                              void* d_out, int out_size)
{
    const float* x  = (const float*)d_in[0];
    const float* wq = (const float*)d_in[1];
    const float* bq = (const float*)d_in[2];
    const float* wk = (const float*)d_in[3];
    const float* bk = (const float*)d_in[4];
    const float* wv = (const float*)d_in[5];
    const float* bv = (const float*)d_in[6];
    const float* wo = (const float*)d_in[7];
    const float* bo = (const float*)d_in[8];
    float* out = (float*)d_out;

    float *qp, *kp, *vp, *aop;
    cudaGetSymbolAddress((void**)&qp,  g_q);
    cudaGetSymbolAddress((void**)&kp,  g_k);
    cudaGetSymbolAddress((void**)&vp,  g_v);
    cudaGetSymbolAddress((void**)&aop, g_ao);

    cudaFuncSetAttribute(gemm_tc<true>,
                         cudaFuncAttributeMaxDynamicSharedMemorySize, GEMM_SMEM);
    cudaFuncSetAttribute(gemm_tc<false>,
                         cudaFuncAttributeMaxDynamicSharedMemorySize, GEMM_SMEM);
    cudaFuncSetAttribute(attn_tc,
                         cudaFuncAttributeMaxDynamicSharedMemorySize, ATT_SMEM);

    rope_table_kernel<<<SEQ, 32>>>();

    // fused Q/K/V projection GEMM
    dim3 fgrid(24, MTOT / 128);
    gemm_tc<true><<<fgrid, 256, GEMM_SMEM>>>(
        x, wq, bq, qp, wk, bk, kp, wv, bv, vp);

    dim3 agrid(SEQ / 64, NB * NH);      // (32, 32)
    attn_tc<<<agrid, 128, ATT_SMEM>>>();

    // output projection
    dim3 ogrid(8, MTOT / 128);
    gemm_tc<false><<<ogrid, 256, GEMM_SMEM>>>(
        aop, wo, bo, out, nullptr, nullptr, nullptr, nullptr, nullptr, nullptr);
}

// round 6
// speedup vs baseline: 1.0083x; 1.0083x over previous
#include <cuda_runtime.h>
#include <math.h>
#include <stdint.h>

#define DM 1024
#define SEQ 2048
#define NB 2
#define NH 16
#define HD 64
#define MTOT (NB*SEQ)   // 4096

// -------- scratch (static device memory; no runtime allocation) ----------
__device__ float g_q[MTOT * DM];     // tf32-bits, RoPE'd, q pre-scaled
__device__ float g_k[MTOT * DM];     // tf32-bits, RoPE'd
__device__ float g_v[MTOT * DM];     // tf32-bits
__device__ float g_ao[MTOT * DM];    // tf32-bits (attention out)
__device__ float g_xc[MTOT * DM];    // tf32-bits of x
__device__ float g_wc[4 * DM * DM];  // tf32-bits of wq,wk,wv,wo
__device__ float g_cos[SEQ * (HD / 2)];
__device__ float g_sin[SEQ * (HD / 2)];

// -------------------- helpers ---------------------
__device__ __forceinline__ uint32_t f2tf32(float x) {
    uint32_t r;
    asm("cvt.rna.tf32.f32 %0, %1;" : "=r"(r) : "f"(x));
    return r;
}

__device__ __forceinline__ void mma8(float* c, const uint32_t* a,
                                     uint32_t b0, uint32_t b1) {
    asm volatile(
        "mma.sync.aligned.m16n8k8.row.col.f32.tf32.tf32.f32 "
        "{%0,%1,%2,%3}, {%4,%5,%6,%7}, {%8,%9}, {%0,%1,%2,%3};\n"
        : "+f"(c[0]), "+f"(c[1]), "+f"(c[2]), "+f"(c[3])
        : "r"(a[0]), "r"(a[1]), "r"(a[2]), "r"(a[3]), "r"(b0), "r"(b1));
}

__device__ __forceinline__ void cp16(uint32_t saddr, const void* g) {
    asm volatile("cp.async.cg.shared.global [%0], [%1], 16;\n"
                 :: "r"(saddr), "l"(g));
}
__device__ __forceinline__ void cp_commit() {
    asm volatile("cp.async.commit_group;\n");
}
template <int N>
__device__ __forceinline__ void cp_wait() {
    asm volatile("cp.async.wait_group %0;\n" :: "n"(N));
}

// -------------------- RoPE tables (double precision) ---------------------
__global__ void rope_table_kernel() {
    int p = threadIdx.x;
    int s = blockIdx.x;
    double freq = pow(10000.0, -(double)(2 * p) / 64.0);
    double ang = (double)s * freq;
    g_cos[s * 32 + p] = (float)cos(ang);
    g_sin[s * 32 + p] = (float)sin(ang);
}

// ---------------- one-shot tf32 conversion of x + weights ----------------
#define X4 (MTOT * DM / 4)     // 1M float4
#define W4 (DM * DM / 4)       // 256K float4
__global__ __launch_bounds__(256) void conv_kernel(
    const float* __restrict__ x,  const float* __restrict__ wq,
    const float* __restrict__ wk, const float* __restrict__ wv,
    const float* __restrict__ wo)
{
    int i = blockIdx.x * 256 + threadIdx.x;
    const float4* src;
    uint4* dst;
    int off;
    if (i < X4)                { src = (const float4*)x;  dst = (uint4*)g_xc;            off = i; }
    else if (i < X4 + W4)      { src = (const float4*)wq; dst = (uint4*)g_wc;            off = i - X4; }
    else if (i < X4 + 2 * W4)  { src = (const float4*)wk; dst = (uint4*)(g_wc + DM*DM);  off = i - X4 - W4; }
    else if (i < X4 + 3 * W4)  { src = (const float4*)wv; dst = (uint4*)(g_wc + 2*DM*DM); off = i - X4 - 2*W4; }
    else                       { src = (const float4*)wo; dst = (uint4*)(g_wc + 3*DM*DM); off = i - X4 - 3*W4; }
    float4 v = src[off];
    dst[off] = make_uint4(f2tf32(v.x), f2tf32(v.y), f2tf32(v.z), f2tf32(v.w));
}

// ------------- tf32 GEMM, cp.async 3-stage pipeline ----------------------
// out = Xc @ Wc^T + b ; Xc/Wc are pre-converted tf32-bit arrays.
// Block 128x128, BK=32, 8 warps (warp tile 64x32), 2 CTAs/SM.
// MODE 0: plain fp32 output (out-projection).
// MODE 1: fused QKV — blockIdx.x>>3 selects {q,k,v}; epilogue does bias,
//         RoPE (q,k), 1/8 scale (q), and writes tf32 bits.
#define GSTR 36
#define STG_WORDS (128 * GSTR)                 // 4608
#define STAGE_WORDS (2 * STG_WORDS)            // A+B
#define NSTAGE 3
#define GEMM_SMEM (NSTAGE * STAGE_WORDS * 4)   // 110592 B

template <int MODE>
__global__ __launch_bounds__(256, 2) void gemm_tc(
    const float* __restrict__ X,  const float* __restrict__ Wbase,
    const float* __restrict__ Bq, const float* __restrict__ Bk,
    const float* __restrict__ Bv, float* __restrict__ Oq,
    float* __restrict__ Ok, float* __restrict__ Ov)
{
    extern __shared__ __align__(16) uint32_t gsm[];

    const float* W;
    const float* bias;
    float* out;
    int sel = 0;
    int bx = blockIdx.x;
    if (MODE == 1) {
        sel  = bx >> 3;
        W    = Wbase + (size_t)sel * DM * DM;
        bias = sel == 0 ? Bq : (sel == 1 ? Bk : Bv);
        out  = sel == 0 ? Oq : (sel == 1 ? Ok : Ov);
        bx &= 7;
    } else {
        W = Wbase; bias = Bq; out = Oq;
    }

    const int tid  = threadIdx.x;
    const int lane = tid & 31;
    const int wid  = tid >> 5;
    const int g    = lane >> 2;
    const int tg   = lane & 3;
    const int wm   = (wid & 1) * 64;
    const int wn   = (wid >> 1) * 32;
    const int m0   = blockIdx.y * 128;
    const int n0   = bx * 128;

    const uint32_t sbase = (uint32_t)__cvta_generic_to_shared(gsm);

    // per-thread cp.async source rows / smem offsets (4 chunks each for A,B)
    const int r_ld  = tid >> 1;                  // 0..127 (two chunks per row pair)
    const int k4_ld = (tid & 1) * 4;             // chunk col group: 0 or 4
    // each thread copies rows r_ld with k4 = k4_ld..k4_ld+3
    // A chunk (r, k4): gmem X[(m0+r)*DM + kt + k4*4], smem (r*GSTR + k4*4)

    float acc[4][4][4];
#pragma unroll
    for (int mi = 0; mi < 4; mi++)
#pragma unroll
        for (int ni = 0; ni < 4; ni++)
#pragma unroll
            for (int q = 0; q < 4; q++) acc[mi][ni][q] = 0.0f;

    // stage issue: 8 cp.async per thread (4 A + 4 B)
    auto issue = [&](int slot, int kt) {
        uint32_t a_s = sbase + (uint32_t)(slot * STAGE_WORDS) * 4;
        uint32_t b_s = a_s + STG_WORDS * 4;
        const float* Xp = X + (size_t)(m0 + r_ld) * DM + kt;
        const float* Wp = W + (size_t)(n0 + r_ld) * DM + kt;
#pragma unroll
        for (int c = 0; c < 4; c++) {
            int k4 = k4_ld + c;
            cp16(a_s + (uint32_t)(r_ld * GSTR + k4 * 4) * 4, Xp + k4 * 4);
            cp16(b_s + (uint32_t)(r_ld * GSTR + k4 * 4) * 4, Wp + k4 * 4);
        }
        cp_commit();
    };

    issue(0, 0);
    issue(1, 32);
    issue(2, 64);

    int slot = 0;
    for (int kt = 0; kt < DM; kt += 32) {
        cp_wait<2>();
        __syncthreads();

        const uint32_t* As = gsm + slot * STAGE_WORDS;
        const uint32_t* Bs = As + STG_WORDS;
#pragma unroll
        for (int ks = 0; ks < 32; ks += 8) {
            uint32_t a[4][4];
#pragma unroll
            for (int mi = 0; mi < 4; mi++) {
                int r0 = wm + mi * 16 + g;
                a[mi][0] = As[r0 * GSTR + ks + tg];
                a[mi][1] = As[(r0 + 8) * GSTR + ks + tg];
                a[mi][2] = As[r0 * GSTR + ks + tg + 4];
                a[mi][3] = As[(r0 + 8) * GSTR + ks + tg + 4];
            }
#pragma unroll
            for (int ni = 0; ni < 4; ni++) {
                int rb = wn + ni * 8 + g;
                uint32_t b0 = Bs[rb * GSTR + ks + tg];
                uint32_t b1 = Bs[rb * GSTR + ks + tg + 4];
#pragma unroll
                for (int mi = 0; mi < 4; mi++)
                    mma8(acc[mi][ni], a[mi], b0, b1);
            }
        }
        __syncthreads();

        if (kt + 96 < DM) issue(slot, kt + 96);
        else              cp_commit();       // keep group counts aligned
        slot = slot == 2 ? 0 : slot + 1;
    }

    // epilogue
    const float qscale = (MODE == 1 && sel == 0) ? 0.125f : 1.0f;
    const bool rope = (MODE == 1) && (sel < 2);
#pragma unroll
    for (int mi = 0; mi < 4; mi++) {
        int row = m0 + wm + mi * 16 + g;
#pragma unroll
        for (int ni = 0; ni < 4; ni++) {
            int col = n0 + wn + ni * 8 + 2 * tg;
            float b0 = bias[col], b1 = bias[col + 1];
            float v0 = acc[mi][ni][0] + b0;
            float v1 = acc[mi][ni][1] + b1;
            float v2 = acc[mi][ni][2] + b0;
            float v3 = acc[mi][ni][3] + b1;
            if (rope) {
                int pr = (col & 63) >> 1;
                int s0 = row & (SEQ - 1);
                int s1 = (row + 8) & (SEQ - 1);
                float c0 = g_cos[s0 * 32 + pr], sn0 = g_sin[s0 * 32 + pr];
                float c1 = g_cos[s1 * 32 + pr], sn1 = g_sin[s1 * 32 + pr];
                float e = v0, o = v1;
                v0 = e * c0 - o * sn0;
                v1 = o * c0 + e * sn0;
                e = v2; o = v3;
                v2 = e * c1 - o * sn1;
                v3 = o * c1 + e * sn1;
            }
            if (MODE == 1) {
                *(uint2*)&out[(size_t)row * DM + col] =
                    make_uint2(f2tf32(v0 * qscale), f2tf32(v1 * qscale));
                *(uint2*)&out[(size_t)(row + 8) * DM + col] =
                    make_uint2(f2tf32(v2 * qscale), f2tf32(v3 * qscale));
            } else {
                *(float2*)&out[(size_t)row * DM + col]       = make_float2(v0, v1);
                *(float2*)&out[(size_t)(row + 8) * DM + col] = make_float2(v2, v3);
            }
        }
    }
}

// --------------------------- flash attention (tf32 MMA) ------------------
// Inputs g_q/g_k/g_v are already tf32 bits (q pre-scaled) -> staging is a
// pure copy. Output written as tf32 bits for the out-projection GEMM.
// grid: (SEQ/128, NB*NH), 128 threads = 4 warps; warp owns 32 query rows.
#define QSTR 68
#define VSTR 72
#define QS_OFF 0
#define KS_OFF (128 * QSTR)
#define VS_OFF (KS_OFF + 64 * QSTR)
#define PS_OFF (VS_OFF + 64 * VSTR)
#define ATT_WORDS (PS_OFF + 128 * QSTR)
#define ATT_SMEM (ATT_WORDS * 4)

__global__ __launch_bounds__(128) void attn_tc()
{
    extern __shared__ __align__(16) uint32_t att_sm[];
    uint32_t* Qs = att_sm + QS_OFF;   // [128][68]
    uint32_t* Ks = att_sm + KS_OFF;   // [64][68]
    uint32_t* Vs = att_sm + VS_OFF;   // [64][72]
    uint32_t* Ps = att_sm + PS_OFF;   // [128][68]

    const int tid  = threadIdx.x;
    const int lane = tid & 31;
    const int wid  = tid >> 5;
    const int g    = lane >> 2;
    const int tg   = lane & 3;
    const int wm   = wid * 32;

    const int q0 = blockIdx.x * 128;
    const int bh = blockIdx.y;
    const int b  = bh >> 4;
    const int h  = bh & 15;

    const size_t base = (size_t)b * SEQ * DM + (size_t)h * HD;

    // copy Q tile (128 x 64) — already scaled + tf32
#pragma unroll
    for (int i = 0; i < 16; i++) {
        int f = tid + i * 128;
        int s = f >> 4, dq = f & 15;
        *(uint4*)&Qs[s * QSTR + dq * 4] =
            *(const uint4*)&g_q[base + (size_t)(q0 + s) * DM + dq * 4];
    }

    float o[2][8][4];
    float mrow[4], lrow[4];
#pragma unroll
    for (int i = 0; i < 4; i++) { mrow[i] = -1e30f; lrow[i] = 0.0f; }
#pragma unroll
    for (int mi = 0; mi < 2; mi++)
#pragma unroll
        for (int ni = 0; ni < 8; ni++)
#pragma unroll
            for (int q = 0; q < 4; q++) o[mi][ni][q] = 0.0f;

    for (int kv0 = 0; kv0 < SEQ; kv0 += 64) {
#pragma unroll
        for (int i = 0; i < 8; i++) {
            int f = tid + i * 128;
            int s = f >> 4, dq = f & 15;
            *(uint4*)&Ks[s * QSTR + dq * 4] =
                *(const uint4*)&g_k[base + (size_t)(kv0 + s) * DM + dq * 4];
            *(uint4*)&Vs[s * VSTR + dq * 4] =
                *(const uint4*)&g_v[base + (size_t)(kv0 + s) * DM + dq * 4];
        }
        __syncthreads();

        // ---- S = Q @ K^T ----
        float sc[2][8][4];
#pragma unroll
        for (int mi = 0; mi < 2; mi++)
#pragma unroll
            for (int ni = 0; ni < 8; ni++)
#pragma unroll
                for (int q = 0; q < 4; q++) sc[mi][ni][q] = 0.0f;

#pragma unroll
        for (int ks = 0; ks < 64; ks += 8) {
            uint32_t a[2][4];
#pragma unroll
            for (int mi = 0; mi < 2; mi++) {
                int r0 = wm + mi * 16 + g;
                a[mi][0] = Qs[r0 * QSTR + ks + tg];
                a[mi][1] = Qs[(r0 + 8) * QSTR + ks + tg];
                a[mi][2] = Qs[r0 * QSTR + ks + tg + 4];
                a[mi][3] = Qs[(r0 + 8) * QSTR + ks + tg + 4];
            }
#pragma unroll
            for (int ni = 0; ni < 8; ni++) {
                int rb = ni * 8 + g;
                uint32_t b0 = Ks[rb * QSTR + ks + tg];
                uint32_t b1 = Ks[rb * QSTR + ks + tg + 4];
#pragma unroll
                for (int mi = 0; mi < 2; mi++)
                    mma8(sc[mi][ni], a[mi], b0, b1);
            }
        }

        // ---- online softmax ----
#pragma unroll
        for (int mi = 0; mi < 2; mi++) {
#pragma unroll
            for (int hf = 0; hf < 2; hf++) {
                int idx = mi * 2 + hf;
                float vmax = -1e30f;
#pragma unroll
                for (int ni = 0; ni < 8; ni++) {
                    vmax = fmaxf(vmax, sc[mi][ni][hf * 2]);
                    vmax = fmaxf(vmax, sc[mi][ni][hf * 2 + 1]);
                }
                vmax = fmaxf(vmax, __shfl_xor_sync(0xffffffffu, vmax, 1));
                vmax = fmaxf(vmax, __shfl_xor_sync(0xffffffffu, vmax, 2));
                float nm = fmaxf(mrow[idx], vmax);
                float alpha = __expf(mrow[idx] - nm);
                mrow[idx] = nm;
                float sum = 0.0f;
                int row = wm + mi * 16 + hf * 8 + g;
#pragma unroll
                for (int ni = 0; ni < 8; ni++) {
                    float px = __expf(sc[mi][ni][hf * 2]     - nm);
                    float py = __expf(sc[mi][ni][hf * 2 + 1] - nm);
                    sum += px + py;
                    *(uint2*)&Ps[row * QSTR + ni * 8 + 2 * tg] =
                        make_uint2(f2tf32(px), f2tf32(py));
                }
                sum += __shfl_xor_sync(0xffffffffu, sum, 1);
                sum += __shfl_xor_sync(0xffffffffu, sum, 2);
                lrow[idx] = lrow[idx] * alpha + sum;
#pragma unroll
                for (int ni = 0; ni < 8; ni++) {
                    o[mi][ni][hf * 2]     *= alpha;
                    o[mi][ni][hf * 2 + 1] *= alpha;
                }
            }
        }
        __syncwarp();

        // ---- O += P @ V ----
#pragma unroll
        for (int ks = 0; ks < 64; ks += 8) {
            uint32_t a[2][4];
#pragma unroll
            for (int mi = 0; mi < 2; mi++) {
                int r0 = wm + mi * 16 + g;
                a[mi][0] = Ps[r0 * QSTR + ks + tg];
                a[mi][1] = Ps[(r0 + 8) * QSTR + ks + tg];
                a[mi][2] = Ps[r0 * QSTR + ks + tg + 4];
                a[mi][3] = Ps[(r0 + 8) * QSTR + ks + tg + 4];
            }
#pragma unroll
            for (int ni = 0; ni < 8; ni++) {
                uint32_t b0 = Vs[(ks + tg) * VSTR + ni * 8 + g];
                uint32_t b1 = Vs[(ks + tg + 4) * VSTR + ni * 8 + g];
#pragma unroll
                for (int mi = 0; mi < 2; mi++)
                    mma8(o[mi][ni], a[mi], b0, b1);
            }
        }
        __syncthreads();
    }

    // normalize + store tf32 bits (consumed by out-proj GEMM)
    float inv[4];
#pragma unroll
    for (int i = 0; i < 4; i++) inv[i] = 1.0f / lrow[i];
#pragma unroll
    for (int mi = 0; mi < 2; mi++) {
        int row = q0 + wm + mi * 16 + g;
#pragma unroll
        for (int ni = 0; ni < 8; ni++) {
            int col = ni * 8 + 2 * tg;
            *(uint2*)&g_ao[base + (size_t)row * DM + col] =
                make_uint2(f2tf32(o[mi][ni][0] * inv[mi * 2]),
                           f2tf32(o[mi][ni][1] * inv[mi * 2]));
            *(uint2*)&g_ao[base + (size_t)(row + 8) * DM + col] =
                make_uint2(f2tf32(o[mi][ni][2] * inv[mi * 2 + 1]),
                           f2tf32(o[mi][ni][3] * inv[mi * 2 + 1]));
        }
    }
}

// ------------------------------- launch ----------------------------------
extern "C" void kernel_launch(void* const* d_in, const int* in_sizes, int n_in,
                              void* d_out, int out_size)
{
    const float* x  = (const float*)d_in[0];
    const float* wq = (const float*)d_in[1];
    const float* bq = (const float*)d_in[2];
    const float* wk = (const float*)d_in[3];
    const float* bk = (const float*)d_in[4];
    const float* wv = (const float*)d_in[5];
    const float* bv = (const float*)d_in[6];
    const float* wo = (const float*)d_in[7];
    const float* bo = (const float*)d_in[8];
    float* out = (float*)d_out;

    float *qp, *kp, *vp, *aop, *xcp, *wcp;
    cudaGetSymbolAddress((void**)&qp,  g_q);
    cudaGetSymbolAddress((void**)&kp,  g_k);
    cudaGetSymbolAddress((void**)&vp,  g_v);
    cudaGetSymbolAddress((void**)&aop, g_ao);
    cudaGetSymbolAddress((void**)&xcp, g_xc);
    cudaGetSymbolAddress((void**)&wcp, g_wc);

    cudaFuncSetAttribute(gemm_tc<0>,
                         cudaFuncAttributeMaxDynamicSharedMemorySize, GEMM_SMEM);
    cudaFuncSetAttribute(gemm_tc<1>,
                         cudaFuncAttributeMaxDynamicSharedMemorySize, GEMM_SMEM);
    cudaFuncSetAttribute(attn_tc,
                         cudaFuncAttributeMaxDynamicSharedMemorySize, ATT_SMEM);

    rope_table_kernel<<<SEQ, 32>>>();
    conv_kernel<<<(X4 + 4 * W4) / 256, 256>>>(x, wq, wk, wv, wo);

    // fused Q/K/V projection (reads g_xc, g_wc[0..3))
    dim3 fgrid(24, MTOT / 128);
    gemm_tc<1><<<fgrid, 256, GEMM_SMEM>>>(
        xcp, wcp, bq, bk, bv, qp, kp, vp);

    dim3 agrid(SEQ / 128, NB * NH);     // (16, 32)
    attn_tc<<<agrid, 128, ATT_SMEM>>>();

    // output projection (reads g_ao, g_wc[3])
    dim3 ogrid(8, MTOT / 128);
    gemm_tc<0><<<ogrid, 256, GEMM_SMEM>>>(
        aop, wcp + (size_t)3 * DM * DM, bo, nullptr, nullptr, out,
        nullptr, nullptr);
}

// round 8
// speedup vs baseline: 2.4411x; 2.4209x over previous
#include <cuda_runtime.h>
#include <cuda_fp16.h>
#include <math.h>
#include <stdint.h>

#define DM 1024
#define SEQ 2048
#define NB 2
#define NH 16
#define HD 64
#define MTOT (NB*SEQ)   // 4096

// -------- scratch (static device memory; no runtime allocation) ----------
__device__ __half g_qh[MTOT * DM];     // RoPE'd, pre-scaled by 1/8
__device__ __half g_kh[MTOT * DM];     // RoPE'd
__device__ __half g_vh[MTOT * DM];
__device__ __half g_aoh[MTOT * DM];    // attention output
__device__ __half g_xh[MTOT * DM];     // fp16 x
__device__ __half g_wh[4 * DM * DM];   // fp16 wq,wk,wv,wo
__device__ float g_cos[SEQ * 32];
__device__ float g_sin[SEQ * 32];

// -------------------- helpers ---------------------
__device__ __forceinline__ uint32_t s2u(const void* p) {
    return (uint32_t)__cvta_generic_to_shared(p);
}

__device__ __forceinline__ void ldsm4(uint32_t* r, uint32_t addr) {
    asm volatile("ldmatrix.sync.aligned.m8n8.x4.shared.b16 {%0,%1,%2,%3}, [%4];"
                 : "=r"(r[0]), "=r"(r[1]), "=r"(r[2]), "=r"(r[3]) : "r"(addr));
}
__device__ __forceinline__ void ldsm4t(uint32_t* r, uint32_t addr) {
    asm volatile("ldmatrix.sync.aligned.m8n8.x4.trans.shared.b16 {%0,%1,%2,%3}, [%4];"
                 : "=r"(r[0]), "=r"(r[1]), "=r"(r[2]), "=r"(r[3]) : "r"(addr));
}

__device__ __forceinline__ void mma16(float* c, const uint32_t* a,
                                      uint32_t b0, uint32_t b1) {
    asm volatile(
        "mma.sync.aligned.m16n8k16.row.col.f32.f16.f16.f32 "
        "{%0,%1,%2,%3}, {%4,%5,%6,%7}, {%8,%9}, {%0,%1,%2,%3};\n"
        : "+f"(c[0]), "+f"(c[1]), "+f"(c[2]), "+f"(c[3])
        : "r"(a[0]), "r"(a[1]), "r"(a[2]), "r"(a[3]), "r"(b0), "r"(b1));
}

__device__ __forceinline__ void cp16(uint32_t saddr, const void* g) {
    asm volatile("cp.async.cg.shared.global [%0], [%1], 16;\n" :: "r"(saddr), "l"(g));
}
__device__ __forceinline__ void cp_commit() {
    asm volatile("cp.async.commit_group;\n");
}
template <int N>
__device__ __forceinline__ void cp_wait() {
    asm volatile("cp.async.wait_group %0;\n" :: "n"(N));
}

__device__ __forceinline__ uint32_t packh2(float a, float b) {
    __half2 h = __floats2half2_rn(a, b);
    return *(uint32_t*)&h;
}

// -------------------- RoPE tables (double precision) ---------------------
__global__ void rope_table_kernel() {
    int p = threadIdx.x;
    int s = blockIdx.x;
    double freq = pow(10000.0, -(double)(2 * p) / 64.0);
    double ang = (double)s * freq;
    g_cos[s * 32 + p] = (float)cos(ang);
    g_sin[s * 32 + p] = (float)sin(ang);
}

// ---------------- one-shot fp16 conversion of x + weights ----------------
#define XF4 (MTOT * DM / 4)
#define WF4 (DM * DM / 4)
__global__ __launch_bounds__(256) void conv_kernel(
    const float* __restrict__ x,  const float* __restrict__ wq,
    const float* __restrict__ wk, const float* __restrict__ wv,
    const float* __restrict__ wo)
{
    int i = blockIdx.x * 256 + threadIdx.x;
    const float4* src;
    __half* dst;
    int off;
    if (i < XF4)               { src = (const float4*)x;  dst = g_xh;              off = i; }
    else if (i < XF4 + WF4)    { src = (const float4*)wq; dst = g_wh;              off = i - XF4; }
    else if (i < XF4 + 2*WF4)  { src = (const float4*)wk; dst = g_wh + DM*DM;      off = i - XF4 - WF4; }
    else if (i < XF4 + 3*WF4)  { src = (const float4*)wv; dst = g_wh + 2*DM*DM;    off = i - XF4 - 2*WF4; }
    else                       { src = (const float4*)wo; dst = g_wh + 3*DM*DM;    off = i - XF4 - 3*WF4; }
    float4 v = src[off];
    uint2 u = make_uint2(packh2(v.x, v.y), packh2(v.z, v.w));
    *(uint2*)&dst[(size_t)off * 4] = u;
}

// ------------- fp16 tensor-core GEMM: out = X @ W^T + b ------------------
// Block 128x128, BK=64, 256 thr / 8 warps, warp tile 64x32, 2 CTAs/SM.
// Dynamic smem: 2 bufs x (A+B) x 128x72 halves = 73728 B.
#define GSTR 72
#define GBUF (128 * GSTR)                 // halves per A (or B) buffer
#define GEMM_SMEM (4 * GBUF * 2)          // bytes

template <int MODE>
__global__ __launch_bounds__(256, 2) void gemm_h(
    const __half* __restrict__ X,  const __half* __restrict__ Wbase,
    const float* __restrict__ Bq,  const float* __restrict__ Bk,
    const float* __restrict__ Bv,  void* __restrict__ Oq,
    void* __restrict__ Ok, void* __restrict__ Ov)
{
    extern __shared__ __align__(16) __half gsm[];
    __half* Ah[2] = {gsm,            gsm + GBUF};
    __half* Bh[2] = {gsm + 2 * GBUF, gsm + 3 * GBUF};

    const __half* W;
    const float* bias;
    void* out;
    int sel = 0;
    int bx = blockIdx.x;
    if (MODE == 1) {
        sel  = bx >> 3;
        W    = Wbase + (size_t)sel * DM * DM;
        bias = sel == 0 ? Bq : (sel == 1 ? Bk : Bv);
        out  = sel == 0 ? Oq : (sel == 1 ? Ok : Ov);
        bx &= 7;
    } else {
        W = Wbase; bias = Bq; out = Oq;
    }

    const int tid  = threadIdx.x;
    const int lane = tid & 31;
    const int wid  = tid >> 5;
    const int g    = lane >> 2;
    const int tg   = lane & 3;
    const int wm   = (wid & 1) * 64;
    const int wn   = (wid >> 1) * 32;
    const int m0   = blockIdx.y * 128;
    const int n0   = bx * 128;

    const int a_r = ((lane >> 3) & 1) * 8 + (lane & 7);
    const int a_c = (lane >> 4) * 8;
    const int b_r = (lane >> 4) * 8 + (lane & 7);
    const int b_c = ((lane >> 3) & 1) * 8;

    float acc[4][4][4];
#pragma unroll
    for (int mi = 0; mi < 4; mi++)
#pragma unroll
        for (int ni = 0; ni < 4; ni++)
#pragma unroll
            for (int q = 0; q < 4; q++) acc[mi][ni][q] = 0.0f;

    auto issue = [&](int buf, int kt) {
#pragma unroll
        for (int i = 0; i < 4; i++) {
            int f = tid + i * 256;
            int r = f >> 3, c8 = f & 7;
            cp16(s2u(&Ah[buf][r * GSTR + c8 * 8]),
                 &X[(size_t)(m0 + r) * DM + kt + c8 * 8]);
            cp16(s2u(&Bh[buf][r * GSTR + c8 * 8]),
                 &W[(size_t)(n0 + r) * DM + kt + c8 * 8]);
        }
        cp_commit();
    };

    issue(0, 0);

    for (int t = 0; t < 16; t++) {
        if (t < 15) issue((t + 1) & 1, (t + 1) * 64);
        else        cp_commit();
        cp_wait<1>();
        __syncthreads();

        const __half* As = Ah[t & 1];
        const __half* Bs = Bh[t & 1];
#pragma unroll
        for (int kc = 0; kc < 4; kc++) {
            uint32_t af[4][4];
#pragma unroll
            for (int mi = 0; mi < 4; mi++)
                ldsm4(af[mi], s2u(&As[(wm + mi * 16 + a_r) * GSTR + kc * 16 + a_c]));
#pragma unroll
            for (int np = 0; np < 2; np++) {
                uint32_t bf[4];
                ldsm4(bf, s2u(&Bs[(wn + np * 16 + b_r) * GSTR + kc * 16 + b_c]));
#pragma unroll
                for (int mi = 0; mi < 4; mi++) {
                    mma16(acc[mi][2 * np],     af[mi], bf[0], bf[1]);
                    mma16(acc[mi][2 * np + 1], af[mi], bf[2], bf[3]);
                }
            }
        }
        __syncthreads();
    }

    // epilogue
    const float qscale = (MODE == 1 && sel == 0) ? 0.125f : 1.0f;
    const bool rope = (MODE == 1) && (sel < 2);
#pragma unroll
    for (int mi = 0; mi < 4; mi++) {
        int row = m0 + wm + mi * 16 + g;
#pragma unroll
        for (int ni = 0; ni < 4; ni++) {
            int col = n0 + wn + ni * 8 + 2 * tg;
            float b0 = bias[col], b1 = bias[col + 1];
            float v0 = acc[mi][ni][0] + b0;
            float v1 = acc[mi][ni][1] + b1;
            float v2 = acc[mi][ni][2] + b0;
            float v3 = acc[mi][ni][3] + b1;
            if (rope) {
                int pr = (col & 63) >> 1;
                int s0 = row & (SEQ - 1);
                int s1 = (row + 8) & (SEQ - 1);
                float c0 = g_cos[s0 * 32 + pr], sn0 = g_sin[s0 * 32 + pr];
                float c1 = g_cos[s1 * 32 + pr], sn1 = g_sin[s1 * 32 + pr];
                float e = v0, o = v1;
                v0 = e * c0 - o * sn0;
                v1 = o * c0 + e * sn0;
                e = v2; o = v3;
                v2 = e * c1 - o * sn1;
                v3 = o * c1 + e * sn1;
            }
            if (MODE == 1) {
                __half* oh = (__half*)out;
                *(uint32_t*)&oh[(size_t)row * DM + col] =
                    packh2(v0 * qscale, v1 * qscale);
                *(uint32_t*)&oh[(size_t)(row + 8) * DM + col] =
                    packh2(v2 * qscale, v3 * qscale);
            } else {
                float* of = (float*)out;
                *(float2*)&of[(size_t)row * DM + col]       = make_float2(v0, v1);
                *(float2*)&of[(size_t)(row + 8) * DM + col] = make_float2(v2, v3);
            }
        }
    }
}

// --------------------------- flash attention (fp16 MMA) ------------------
// grid (SEQ/128, NB*NH), 256 thr / 8 warps, warp owns 16 query rows.
// Q fragments register-resident; S C-frags -> PV A-frags in-register;
// V via ldmatrix.trans; K/V double-buffered cp.async.
// Dynamic smem: Q 128x72 + 2x(K 64x72 + V 64x72) halves = 55296 B.
#define ASTR 72
#define AQ_WORDS (128 * ASTR)
#define AKV_WORDS (64 * ASTR)
#define ATT_SMEM ((AQ_WORDS + 4 * AKV_WORDS) * 2)

__global__ __launch_bounds__(256, 2) void attn_h()
{
    extern __shared__ __align__(16) __half asmem[];
    __half* Qs    = asmem;
    __half* Ks[2] = {asmem + AQ_WORDS,                 asmem + AQ_WORDS + AKV_WORDS};
    __half* Vs[2] = {asmem + AQ_WORDS + 2 * AKV_WORDS, asmem + AQ_WORDS + 3 * AKV_WORDS};

    const int tid  = threadIdx.x;
    const int lane = tid & 31;
    const int wid  = tid >> 5;       // 0..7
    const int g    = lane >> 2;
    const int tg   = lane & 3;
    const int wm   = wid * 16;

    const int a_r = ((lane >> 3) & 1) * 8 + (lane & 7);
    const int a_c = (lane >> 4) * 8;
    const int b_r = (lane >> 4) * 8 + (lane & 7);
    const int b_c = ((lane >> 3) & 1) * 8;

    const int q0 = blockIdx.x * 128;
    const int bh = blockIdx.y;
    const int b  = bh >> 4;
    const int h  = bh & 15;

    const size_t base = (size_t)b * SEQ * DM + (size_t)h * HD;

    // stage Q tile (128 x 64 halves)
#pragma unroll
    for (int i = 0; i < 4; i++) {
        int f = tid + i * 256;
        int r = f >> 3, c8 = f & 7;
        *(uint4*)&Qs[r * ASTR + c8 * 8] =
            *(const uint4*)&g_qh[base + (size_t)(q0 + r) * DM + c8 * 8];
    }

    auto issue = [&](int buf, int kv0) {
#pragma unroll
        for (int i = 0; i < 2; i++) {
            int f = tid + i * 256;
            int r = f >> 3, c8 = f & 7;
            cp16(s2u(&Ks[buf][r * ASTR + c8 * 8]),
                 &g_kh[base + (size_t)(kv0 + r) * DM + c8 * 8]);
            cp16(s2u(&Vs[buf][r * ASTR + c8 * 8]),
                 &g_vh[base + (size_t)(kv0 + r) * DM + c8 * 8]);
        }
        cp_commit();
    };
    issue(0, 0);
    __syncthreads();   // Qs visible

    uint32_t qf[4][4];
#pragma unroll
    for (int kc = 0; kc < 4; kc++)
        ldsm4(qf[kc], s2u(&Qs[(wm + a_r) * ASTR + kc * 16 + a_c]));

    float o[8][4];
    float mrow[2], lrow[2];
    mrow[0] = mrow[1] = -1e30f;
    lrow[0] = lrow[1] = 0.0f;
#pragma unroll
    for (int ni = 0; ni < 8; ni++)
#pragma unroll
        for (int q = 0; q < 4; q++) o[ni][q] = 0.0f;

    for (int t = 0; t < SEQ / 64; t++) {
        if (t < SEQ / 64 - 1) issue((t + 1) & 1, (t + 1) * 64);
        else                  cp_commit();
        cp_wait<1>();
        __syncthreads();

        const __half* Kt = Ks[t & 1];
        const __half* Vt = Vs[t & 1];

        // ---- S = Q @ K^T ----
        float sc[8][4];
#pragma unroll
        for (int ni = 0; ni < 8; ni++)
#pragma unroll
            for (int q = 0; q < 4; q++) sc[ni][q] = 0.0f;

#pragma unroll
        for (int kc = 0; kc < 4; kc++) {
#pragma unroll
            for (int np = 0; np < 4; np++) {
                uint32_t bf[4];
                ldsm4(bf, s2u(&Kt[(np * 16 + b_r) * ASTR + kc * 16 + b_c]));
                mma16(sc[2 * np],     qf[kc], bf[0], bf[1]);
                mma16(sc[2 * np + 1], qf[kc], bf[2], bf[3]);
            }
        }

        // ---- online softmax ----
#pragma unroll
        for (int hf = 0; hf < 2; hf++) {
            float vmax = -1e30f;
#pragma unroll
            for (int ni = 0; ni < 8; ni++) {
                vmax = fmaxf(vmax, sc[ni][hf * 2]);
                vmax = fmaxf(vmax, sc[ni][hf * 2 + 1]);
            }
            vmax = fmaxf(vmax, __shfl_xor_sync(0xffffffffu, vmax, 1));
            vmax = fmaxf(vmax, __shfl_xor_sync(0xffffffffu, vmax, 2));
            float nm = fmaxf(mrow[hf], vmax);
            float alpha = __expf(mrow[hf] - nm);
            mrow[hf] = nm;
            float sum = 0.0f;
#pragma unroll
            for (int ni = 0; ni < 8; ni++) {
                float px = __expf(sc[ni][hf * 2]     - nm);
                float py = __expf(sc[ni][hf * 2 + 1] - nm);
                sc[ni][hf * 2]     = px;
                sc[ni][hf * 2 + 1] = py;
                sum += px + py;
            }
            sum += __shfl_xor_sync(0xffffffffu, sum, 1);
            sum += __shfl_xor_sync(0xffffffffu, sum, 2);
            lrow[hf] = lrow[hf] * alpha + sum;
#pragma unroll
            for (int ni = 0; ni < 8; ni++) {
                o[ni][hf * 2]     *= alpha;
                o[ni][hf * 2 + 1] *= alpha;
            }
        }

        // ---- O += P @ V : P C-frags -> A-frags in registers ----
#pragma unroll
        for (int kc = 0; kc < 4; kc++) {
            uint32_t pa[4];
            pa[0] = packh2(sc[2 * kc][0],     sc[2 * kc][1]);
            pa[1] = packh2(sc[2 * kc][2],     sc[2 * kc][3]);
            pa[2] = packh2(sc[2 * kc + 1][0], sc[2 * kc + 1][1]);
            pa[3] = packh2(sc[2 * kc + 1][2], sc[2 * kc + 1][3]);
#pragma unroll
            for (int np = 0; np < 4; np++) {
                uint32_t bf[4];
                ldsm4t(bf, s2u(&Vt[(kc * 16 + a_r) * ASTR + np * 16 + a_c]));
                mma16(o[2 * np],     pa, bf[0], bf[1]);
                mma16(o[2 * np + 1], pa, bf[2], bf[3]);
            }
        }
        __syncthreads();
    }

    // normalize + store half
    float inv0 = 1.0f / lrow[0];
    float inv1 = 1.0f / lrow[1];
    int row = q0 + wm + g;
#pragma unroll
    for (int ni = 0; ni < 8; ni++) {
        int col = ni * 8 + 2 * tg;
        *(uint32_t*)&g_aoh[base + (size_t)row * DM + col] =
            packh2(o[ni][0] * inv0, o[ni][1] * inv0);
        *(uint32_t*)&g_aoh[base + (size_t)(row + 8) * DM + col] =
            packh2(o[ni][2] * inv1, o[ni][3] * inv1);
    }
}

// ------------------------------- launch ----------------------------------
extern "C" void kernel_launch(void* const* d_in, const int* in_sizes, int n_in,
                              void* d_out, int out_size)
{
    const float* x  = (const float*)d_in[0];
    const float* wq = (const float*)d_in[1];
    const float* bq = (const float*)d_in[2];
    const float* wk = (const float*)d_in[3];
    const float* bk = (const float*)d_in[4];
    const float* wv = (const float*)d_in[5];
    const float* bv = (const float*)d_in[6];
    const float* wo = (const float*)d_in[7];
    const float* bo = (const float*)d_in[8];
    float* out = (float*)d_out;

    __half *qp, *kp, *vp, *aop, *xhp, *whp;
    cudaGetSymbolAddress((void**)&qp,  g_qh);
    cudaGetSymbolAddress((void**)&kp,  g_kh);
    cudaGetSymbolAddress((void**)&vp,  g_vh);
    cudaGetSymbolAddress((void**)&aop, g_aoh);
    cudaGetSymbolAddress((void**)&xhp, g_xh);
    cudaGetSymbolAddress((void**)&whp, g_wh);

    cudaFuncSetAttribute(gemm_h<0>,
                         cudaFuncAttributeMaxDynamicSharedMemorySize, GEMM_SMEM);
    cudaFuncSetAttribute(gemm_h<1>,
                         cudaFuncAttributeMaxDynamicSharedMemorySize, GEMM_SMEM);
    cudaFuncSetAttribute(attn_h,
                         cudaFuncAttributeMaxDynamicSharedMemorySize, ATT_SMEM);

    rope_table_kernel<<<SEQ, 32>>>();
    conv_kernel<<<(XF4 + 4 * WF4) / 256, 256>>>(x, wq, wk, wv, wo);

    // fused Q/K/V projection
    dim3 fgrid(24, MTOT / 128);
    gemm_h<1><<<fgrid, 256, GEMM_SMEM>>>(xhp, whp, bq, bk, bv, qp, kp, vp);

    dim3 agrid(SEQ / 128, NB * NH);   // (16, 32)
    attn_h<<<agrid, 256, ATT_SMEM>>>();

    // output projection
    dim3 ogrid(8, MTOT / 128);
    gemm_h<0><<<ogrid, 256, GEMM_SMEM>>>(aop, whp + (size_t)3 * DM * DM, bo,
                                         nullptr, nullptr, out, nullptr, nullptr);
}